// round 12
// baseline (speedup 1.0000x reference)
#include <cuda_runtime.h>
#include <cuda_bf16.h>
#include <cstdint>

#define T_STEPS 1024
#define B_SZ    64
#define H_SZ    512
#define IN_SZ   512
#define NCTA    128
#define NSTR    8          // independent batch streams
#define CPS     32         // CTAs per stream
#define BPS     8          // batches per stream
#define UPC     16         // hidden units per CTA (64 gate-rows)
#define HSP     520        // padded row length (bf16 elems)
#define MROWS   65536      // T*B

#define WXS_PL  (64 * HSP)     // Wx plane (ushorts)
#define HS_PL   (8 * HSP)      // h plane per stream (ushorts)
// smem bytes: 2*WXS_PL*2 + 2*2*HS_PL*2 + 2*2*2048*4 = 199168
#define SMEM_REC 199168

// ---------------- scratch ----------------
__device__ unsigned short g_hhi[(size_t)T_STEPS * NSTR * BPS * H_SZ];     // h bf16 hi
__device__ unsigned short g_hlo[(size_t)T_STEPS * NSTR * BPS * H_SZ];     // h bf16 lo
__device__ unsigned       g_arrive[NSTR * CPS];                           // stream flags
__device__ unsigned short g_xhi[(size_t)MROWS * IN_SZ];                   // x bf16 hi
__device__ unsigned short g_xlo[(size_t)MROWS * IN_SZ];                   // x bf16 lo

// ---------------- helpers ----------------
__device__ __forceinline__ float tanh_apx(float x) {
    float y; asm("tanh.approx.f32 %0, %1;" : "=f"(y) : "f"(x)); return y;
}
__device__ __forceinline__ float sig_apx(float x) {
    return fmaf(0.5f, tanh_apx(0.5f * x), 0.5f);
}
__device__ __forceinline__ unsigned smem_u32(const void* p) {
    return (unsigned)__cvta_generic_to_shared(p);
}
__device__ __forceinline__ void cp_async16(unsigned dst, const void* src) {
    asm volatile("cp.async.ca.shared.global [%0], [%1], 16;" :: "r"(dst), "l"(src));
}
__device__ __forceinline__ void cp_commit() {
    asm volatile("cp.async.commit_group;" ::: "memory");
}
__device__ __forceinline__ void cp_wait0() {
    asm volatile("cp.async.wait_group 0;" ::: "memory");
}
__device__ __forceinline__ void flag_release(unsigned* p, unsigned v) {
    asm volatile("st.release.gpu.global.u32 [%0], %1;" :: "l"(p), "r"(v) : "memory");
}
__device__ __forceinline__ unsigned flag_acquire(const unsigned* p) {
    unsigned v;
    asm volatile("ld.acquire.gpu.global.u32 %0, [%1];" : "=r"(v) : "l"(p) : "memory");
    return v;
}
__device__ __forceinline__ void split1(float v, unsigned short& hi, unsigned short& lo) {
    hi = __bfloat16_as_ushort(__float2bfloat16(v));
    float r = v - __bfloat162float(__ushort_as_bfloat16(hi));
    lo = __bfloat16_as_ushort(__float2bfloat16(r));
}
__device__ __forceinline__ void split2(float2 v, unsigned& hi, unsigned& lo) {
    unsigned short hx, lx, hy, ly;
    split1(v.x, hx, lx); split1(v.y, hy, ly);
    hi = (unsigned)hx | ((unsigned)hy << 16);
    lo = (unsigned)lx | ((unsigned)ly << 16);
}
__device__ __forceinline__ void mma16816(float* d, const unsigned* a,
                                         unsigned b0, unsigned b1) {
    asm volatile(
        "mma.sync.aligned.m16n8k16.row.col.f32.bf16.bf16.f32 "
        "{%0,%1,%2,%3}, {%4,%5,%6,%7}, {%8,%9}, {%0,%1,%2,%3};"
        : "+f"(d[0]), "+f"(d[1]), "+f"(d[2]), "+f"(d[3])
        : "r"(a[0]), "r"(a[1]), "r"(a[2]), "r"(a[3]), "r"(b0), "r"(b1));
}

// =====================================================================
// convert_x: split x fp32 -> bf16 hi/lo planes (row = t*64 + b)
// =====================================================================
__global__ __launch_bounds__(256) void convert_x(const float* __restrict__ x) {
    size_t i = ((size_t)blockIdx.x * 256 + threadIdx.x) * 4;
    float4 v = *(const float4*)&x[i];
    unsigned short h[4], l[4];
    split1(v.x, h[0], l[0]); split1(v.y, h[1], l[1]);
    split1(v.z, h[2], l[2]); split1(v.w, h[3], l[3]);
    *(ushort4*)&g_xhi[i] = make_ushort4(h[0], h[1], h[2], h[3]);
    *(ushort4*)&g_xlo[i] = make_ushort4(l[0], l[1], l[2], l[3]);
}

// =====================================================================
// lstm_rec: persistent recurrence with input projection fused into the
// cp.async stage-wait window. R9 two-stream staggered schedule.
// zc parity double buffer: zx(t+1) written at step t by thread (kw,mt,g,t2);
// the SAME thread reads it at t+1 as its h-MMA accumulator init.
// =====================================================================
__global__ __launch_bounds__(512, 1) void lstm_rec(
    const float* __restrict__ Whf, const float* __restrict__ Whi,
    const float* __restrict__ Who, const float* __restrict__ Whg,
    const float* __restrict__ Wxf, const float* __restrict__ Wxi,
    const float* __restrict__ Wxo, const float* __restrict__ Wxg,
    const float* __restrict__ bxf, const float* __restrict__ bxi,
    const float* __restrict__ bxo, const float* __restrict__ bxg,
    const float* __restrict__ bhf, const float* __restrict__ bhi,
    const float* __restrict__ bho, const float* __restrict__ bhg,
    float* __restrict__ out)
{
    extern __shared__ unsigned short dsm[];
    unsigned short* wxs = dsm;                      // [2][64*HSP]  133 KB
    unsigned short* hsA = wxs + 2 * WXS_PL;         // [2][8*HSP]
    unsigned short* hsB = hsA + 2 * HS_PL;          // [2][8*HSP]
    float* zc = (float*)(hsB + 2 * HS_PL);          // [par][stream][2048]  32 KB

    const int tid = threadIdx.x;
    const int ct  = blockIdx.x;
    const int cw  = ct & 31;
    const int sA  = (ct >> 5) * 2;
    const int sB  = sA + 1;
    const int j0  = cw * UPC;
    const int B0A = sA * BPS;
    const int B0B = sB * BPS;

    const int w   = tid >> 5;          // warp 0..15
    const int mt  = w & 3;             // gate
    const int kw  = w >> 2;            // k-slice (128 k)
    const int ln  = tid & 31;
    const int g   = ln >> 2;
    const int t2  = ln & 3;

    // ---- register-stationary split-bf16 Wh A-fragments ----
    const float* whp = (mt == 0) ? Whf : (mt == 1) ? Whi : (mt == 2) ? Who : Whg;
    unsigned a_hi[8][4], a_lo[8][4];
    {
        const float* Wr  = whp + (size_t)(j0 + g) * H_SZ;
        const float* Wr8 = whp + (size_t)(j0 + g + 8) * H_SZ;
        #pragma unroll
        for (int kt = 0; kt < 8; kt++) {
            int kb = kw * 128 + kt * 16 + 2 * t2;
            split2(*(const float2*)&Wr [kb],     a_hi[kt][0], a_lo[kt][0]);
            split2(*(const float2*)&Wr8[kb],     a_hi[kt][1], a_lo[kt][1]);
            split2(*(const float2*)&Wr [kb + 8], a_hi[kt][2], a_lo[kt][2]);
            split2(*(const float2*)&Wr8[kb + 8], a_hi[kt][3], a_lo[kt][3]);
        }
    }

    // ---- Wx slice -> smem planes (row = 16*gate + unit) ----
    for (int idx = tid; idx < 64 * 512; idx += 512) {
        int r = idx >> 9, k = idx & 511;
        int gate = r >> 4, u = r & 15;
        const float* Wp = (gate == 0) ? Wxf : (gate == 1) ? Wxi : (gate == 2) ? Wxo : Wxg;
        unsigned short hi, lo;
        split1(Wp[(size_t)(j0 + u) * IN_SZ + k], hi, lo);
        wxs[r * HSP + k]          = hi;
        wxs[WXS_PL + r * HSP + k] = lo;
    }

    // ---- gate-duty setup (tid<128) ----
    const int ul = (tid & 127) >> 3;
    const int ub = tid & 7;
    float bias[4] = {0.f, 0.f, 0.f, 0.f};
    if (tid < 128) {
        int j = j0 + ul;
        bias[0] = bxf[j] + bhf[j];
        bias[1] = bxi[j] + bhi[j];
        bias[2] = bxo[j] + bho[j];
        bias[3] = bxg[j] + bhg[j];
    }

    const unsigned baseA = flag_acquire(&g_arrive[sA * CPS + cw]);
    const unsigned baseB = flag_acquire(&g_arrive[sB * CPS + cw]);
    __syncthreads();   // wxs visible

    // ---- zx: z_x[tn] fragment for one stream; x read straight from global ----
    auto zx_mma = [&](int tn, int B0, float* zdst) {
        float d[4] = {0.f, 0.f, 0.f, 0.f};
        const unsigned short* wr_hi = wxs + (16 * mt + g) * HSP;
        const unsigned short* wr_lo = wxs + WXS_PL + (16 * mt + g) * HSP;
        const size_t xrow = ((size_t)tn * B_SZ + B0 + g) * IN_SZ;
        #pragma unroll
        for (int kt = 0; kt < 8; kt++) {
            int kb = kw * 128 + kt * 16 + 2 * t2;
            unsigned ah[4], al[4];
            ah[0] = *(const unsigned*)&wr_hi[kb];
            ah[1] = *(const unsigned*)&wr_hi[kb + 8 * HSP];
            ah[2] = *(const unsigned*)&wr_hi[kb + 8];
            ah[3] = *(const unsigned*)&wr_hi[kb + 8 * HSP + 8];
            al[0] = *(const unsigned*)&wr_lo[kb];
            al[1] = *(const unsigned*)&wr_lo[kb + 8 * HSP];
            al[2] = *(const unsigned*)&wr_lo[kb + 8];
            al[3] = *(const unsigned*)&wr_lo[kb + 8 * HSP + 8];
            unsigned xh0 = *(const unsigned*)&g_xhi[xrow + kb];
            unsigned xh1 = *(const unsigned*)&g_xhi[xrow + kb + 8];
            unsigned xl0 = *(const unsigned*)&g_xlo[xrow + kb];
            unsigned xl1 = *(const unsigned*)&g_xlo[xrow + kb + 8];
            mma16816(d, ah, xh0, xh1);
            mma16816(d, al, xh0, xh1);
            mma16816(d, ah, xl0, xl1);
        }
        int r0 = (kw * 64 + 16 * mt + g) * 8 + 2 * t2;
        *(float2*)&zdst[r0]      = make_float2(d[0], d[1]);
        *(float2*)&zdst[r0 + 64] = make_float2(d[2], d[3]);
    };

    // prologue: z_x[0] for both streams
    zx_mma(0, B0A, zc + 0 * 2048);
    zx_mma(0, B0B, zc + 1 * 2048);
    __syncthreads();

    float cA = 0.0f, cB = 0.0f;

    for (int t = 0; t < T_STEPS; t++) {
        const int par = t & 1;
        float* zcurA = zc + (par * 2 + 0) * 2048;
        float* zcurB = zc + (par * 2 + 1) * 2048;
        float* znxtA = zc + ((par ^ 1) * 2 + 0) * 2048;
        float* znxtB = zc + ((par ^ 1) * 2 + 1) * 2048;

        #pragma unroll
        for (int half = 0; half < 2; half++) {
            const int       s    = half ? sB : sA;
            unsigned short* hs   = half ? hsB : hsA;
            float*          zcur = half ? zcurB : zcurA;
            float*          znxt = half ? znxtB : znxtA;
            const unsigned  base = half ? baseB : baseA;
            const int       B0   = half ? B0B : B0A;
            float&          c    = half ? cB : cA;

            if (t > 0) {
                // poll producers of this stream
                if (tid < CPS) {
                    const unsigned* fp = &g_arrive[s * CPS + tid];
                    unsigned target = base + (unsigned)t;
                    while ((int)(flag_acquire(fp) - target) < 0) { }
                }
                __syncthreads();

                // stage h_{t-1}: 1024 x 16B chunks, 2 per thread
                {
                    const size_t srcb = (((size_t)(t - 1) * NSTR + s) * BPS) * H_SZ;
                    #pragma unroll
                    for (int i = 0; i < 2; i++) {
                        int idx = tid + i * 512;
                        int pl = idx >> 9;
                        int b  = (idx >> 6) & 7;
                        int c8 = idx & 63;
                        unsigned dst = smem_u32(hs + pl * HS_PL + b * HSP + c8 * 8);
                        const unsigned short* src = (pl ? g_hlo : g_hhi)
                                                    + srcb + (size_t)b * H_SZ + c8 * 8;
                        cp_async16(dst, src);
                    }
                }
                cp_commit();
            }

            // fused input projection for step t+1 — fills the stage-wait window
            if (t + 1 < T_STEPS) zx_mma(t + 1, B0, znxt);

            if (t > 0) {
                cp_wait0();
                __syncthreads();

                // h-MMA, accumulators initialized from zcur (= z_x[t] partials)
                int r0 = (kw * 64 + 16 * mt + g) * 8 + 2 * t2;
                float d[4];
                { float2 v = *(float2*)&zcur[r0];      d[0] = v.x; d[1] = v.y; }
                { float2 v = *(float2*)&zcur[r0 + 64]; d[2] = v.x; d[3] = v.y; }
                const unsigned short* hr_hi = hs + g * HSP;
                const unsigned short* hr_lo = hs + HS_PL + g * HSP;
                #pragma unroll
                for (int kt = 0; kt < 8; kt++) {
                    int kb = kw * 128 + kt * 16 + 2 * t2;
                    unsigned bh0 = *(const unsigned*)&hr_hi[kb];
                    unsigned bh1 = *(const unsigned*)&hr_hi[kb + 8];
                    unsigned bl0 = *(const unsigned*)&hr_lo[kb];
                    unsigned bl1 = *(const unsigned*)&hr_lo[kb + 8];
                    mma16816(d, a_hi[kt], bh0, bh1);
                    mma16816(d, a_lo[kt], bh0, bh1);
                    mma16816(d, a_hi[kt], bl0, bl1);
                }
                *(float2*)&zcur[r0]      = make_float2(d[0], d[1]);
                *(float2*)&zcur[r0 + 64] = make_float2(d[2], d[3]);
                __syncthreads();
            }

            // gate update (tid<128): z = bias + sum of 4 k-slice partials
            if (tid < 128) {
                float z[4];
                #pragma unroll
                for (int q = 0; q < 4; q++) {
                    int rr = (16 * q + ul) * 8 + ub;
                    z[q] = bias[q] + zcur[rr] + zcur[512 + rr]
                                   + zcur[1024 + rr] + zcur[1536 + rr];
                }
                float f  = sig_apx(z[0]);
                float ii = sig_apx(z[1]);
                float o  = sig_apx(z[2]);
                float gg = tanh_apx(z[3]);
                c        = fmaf(f, c, ii * gg);
                float h  = o * tanh_apx(c);
                int j = j0 + ul;
                int B = s * BPS + ub;
                out[((size_t)t * B_SZ + B) * H_SZ + j] = h;
                unsigned short hh, hl;
                split1(h, hh, hl);
                size_t hb = (((size_t)t * NSTR + s) * BPS + ub) * H_SZ + j;
                g_hhi[hb] = hh;
                g_hlo[hb] = hl;
                if (t == T_STEPS - 1) {
                    size_t tail = (size_t)T_STEPS * B_SZ * H_SZ;
                    out[tail + (size_t)B * H_SZ + j] = h;
                    out[tail + (size_t)B_SZ * H_SZ + (size_t)B * H_SZ + j] = c;
                }
            }
            __syncthreads();
            if (tid == 0)
                flag_release(&g_arrive[s * CPS + cw], base + (unsigned)t + 1u);
        }
    }
}

// =====================================================================
extern "C" void kernel_launch(void* const* d_in, const int* in_sizes, int n_in,
                              void* d_out, int out_size)
{
    const float* x   = (const float*)d_in[0];
    const float* Wxf = (const float*)d_in[1];  const float* bxf = (const float*)d_in[2];
    const float* Whf = (const float*)d_in[3];  const float* bhf = (const float*)d_in[4];
    const float* Wxi = (const float*)d_in[5];  const float* bxi = (const float*)d_in[6];
    const float* Whi = (const float*)d_in[7];  const float* bhi = (const float*)d_in[8];
    const float* Wxo = (const float*)d_in[9];  const float* bxo = (const float*)d_in[10];
    const float* Who = (const float*)d_in[11]; const float* bho = (const float*)d_in[12];
    const float* Wxg = (const float*)d_in[13]; const float* bxg = (const float*)d_in[14];
    const float* Whg = (const float*)d_in[15]; const float* bhg = (const float*)d_in[16];
    float* out = (float*)d_out;

    convert_x<<<(MROWS * IN_SZ) / (256 * 4), 256>>>(x);

    cudaFuncSetAttribute(lstm_rec, cudaFuncAttributeMaxDynamicSharedMemorySize, SMEM_REC);
    lstm_rec<<<NCTA, 512, SMEM_REC>>>(Whf, Whi, Who, Whg,
                                      Wxf, Wxi, Wxo, Wxg,
                                      bxf, bxi, bxo, bxg,
                                      bhf, bhi, bho, bhg,
                                      out);
}

// round 13
// speedup vs baseline: 1.5813x; 1.5813x over previous
#include <cuda_runtime.h>
#include <cuda_bf16.h>
#include <cstdint>

#define T_STEPS 1024
#define B_SZ    64
#define H_SZ    512
#define IN_SZ   512
#define G4      2048
#define NCTA    128
#define NSTR    8          // independent batch streams
#define CPS     32         // CTAs per stream
#define BPS     8          // batches per stream
#define UPC     16         // hidden units per CTA (64 gate-rows)
#define HSP     520        // padded hs row length (bf16) in lstm_rec

#define MROWS   65536      // T*B
#define BKS     24         // xp_mma smem row stride in ushorts (48 B, conflict-free)

// ---------------- scratch ----------------
__device__ float          g_xpT[(size_t)T_STEPS * G4 * B_SZ];             // [t][g][b]
__device__ unsigned short g_hhi[(size_t)T_STEPS * NSTR * BPS * H_SZ];     // h bf16 hi
__device__ unsigned short g_hlo[(size_t)T_STEPS * NSTR * BPS * H_SZ];     // h bf16 lo
__device__ unsigned       g_arrive[NSTR * CPS];                           // stream flags
__device__ unsigned short g_xhi[(size_t)MROWS * IN_SZ];                   // x bf16 hi
__device__ unsigned short g_xlo[(size_t)MROWS * IN_SZ];                   // x bf16 lo
__device__ unsigned short g_whi[(size_t)G4 * IN_SZ];                      // Wx bf16 hi
__device__ unsigned short g_wlo[(size_t)G4 * IN_SZ];                      // Wx bf16 lo
__device__ float          g_bias[G4];                                     // bx + bh

// ---------------- helpers ----------------
__device__ __forceinline__ float tanh_apx(float x) {
    float y; asm("tanh.approx.f32 %0, %1;" : "=f"(y) : "f"(x)); return y;
}
__device__ __forceinline__ float sig_apx(float x) {
    return fmaf(0.5f, tanh_apx(0.5f * x), 0.5f);
}
__device__ __forceinline__ unsigned smem_u32(const void* p) {
    return (unsigned)__cvta_generic_to_shared(p);
}
__device__ __forceinline__ void cp_async16(unsigned dst, const void* src) {
    asm volatile("cp.async.ca.shared.global [%0], [%1], 16;" :: "r"(dst), "l"(src));
}
__device__ __forceinline__ void cp_commit() {
    asm volatile("cp.async.commit_group;" ::: "memory");
}
__device__ __forceinline__ void cp_wait_n(int n) {
    if (n == 0) asm volatile("cp.async.wait_group 0;" ::: "memory");
    else        asm volatile("cp.async.wait_group 1;" ::: "memory");
}
__device__ __forceinline__ void flag_release(unsigned* p, unsigned v) {
    asm volatile("st.release.gpu.global.u32 [%0], %1;" :: "l"(p), "r"(v) : "memory");
}
__device__ __forceinline__ unsigned flag_acquire(const unsigned* p) {
    unsigned v;
    asm volatile("ld.acquire.gpu.global.u32 %0, [%1];" : "=r"(v) : "l"(p) : "memory");
    return v;
}
__device__ __forceinline__ void split1(float v, unsigned short& hi, unsigned short& lo) {
    hi = __bfloat16_as_ushort(__float2bfloat16(v));
    float r = v - __bfloat162float(__ushort_as_bfloat16(hi));
    lo = __bfloat16_as_ushort(__float2bfloat16(r));
}
__device__ __forceinline__ void split2(float2 v, unsigned& hi, unsigned& lo) {
    unsigned short hx, lx, hy, ly;
    split1(v.x, hx, lx); split1(v.y, hy, ly);
    hi = (unsigned)hx | ((unsigned)hy << 16);
    lo = (unsigned)lx | ((unsigned)ly << 16);
}
__device__ __forceinline__ void mma16816(float* d, const unsigned* a,
                                         unsigned b0, unsigned b1) {
    asm volatile(
        "mma.sync.aligned.m16n8k16.row.col.f32.bf16.bf16.f32 "
        "{%0,%1,%2,%3}, {%4,%5,%6,%7}, {%8,%9}, {%0,%1,%2,%3};"
        : "+f"(d[0]), "+f"(d[1]), "+f"(d[2]), "+f"(d[3])
        : "r"(a[0]), "r"(a[1]), "r"(a[2]), "r"(a[3]), "r"(b0), "r"(b1));
}

// =====================================================================
// Converters: split fp32 -> bf16 hi/lo planes
// =====================================================================
__global__ __launch_bounds__(256) void convert_x(const float* __restrict__ x) {
    size_t i = ((size_t)blockIdx.x * 256 + threadIdx.x) * 4;
    float4 v = *(const float4*)&x[i];
    unsigned short h[4], l[4];
    split1(v.x, h[0], l[0]); split1(v.y, h[1], l[1]);
    split1(v.z, h[2], l[2]); split1(v.w, h[3], l[3]);
    *(ushort4*)&g_xhi[i] = make_ushort4(h[0], h[1], h[2], h[3]);
    *(ushort4*)&g_xlo[i] = make_ushort4(l[0], l[1], l[2], l[3]);
}

__global__ __launch_bounds__(128) void convert_w(
    const float* __restrict__ Wx0, const float* __restrict__ Wx1,
    const float* __restrict__ Wx2, const float* __restrict__ Wx3,
    const float* __restrict__ bx0, const float* __restrict__ bx1,
    const float* __restrict__ bx2, const float* __restrict__ bx3,
    const float* __restrict__ bh0, const float* __restrict__ bh1,
    const float* __restrict__ bh2, const float* __restrict__ bh3)
{
    int gidx = blockIdx.x;
    int gate = gidx >> 9, r = gidx & 511;
    const float* W = (gate == 0) ? Wx0 : (gate == 1) ? Wx1 : (gate == 2) ? Wx2 : Wx3;
    size_t base = (size_t)gidx * IN_SZ;
    for (int k = threadIdx.x * 4; k < IN_SZ; k += 128 * 4) {
        float4 v = *(const float4*)&W[(size_t)r * IN_SZ + k];
        unsigned short h[4], l[4];
        split1(v.x, h[0], l[0]); split1(v.y, h[1], l[1]);
        split1(v.z, h[2], l[2]); split1(v.w, h[3], l[3]);
        *(ushort4*)&g_whi[base + k] = make_ushort4(h[0], h[1], h[2], h[3]);
        *(ushort4*)&g_wlo[base + k] = make_ushort4(l[0], l[1], l[2], l[3]);
    }
    if (threadIdx.x == 0) {
        const float* bx = (gate == 0) ? bx0 : (gate == 1) ? bx1 : (gate == 2) ? bx2 : bx3;
        const float* bh = (gate == 0) ? bh0 : (gate == 1) ? bh1 : (gate == 2) ? bh2 : bh3;
        g_bias[gidx] = bx[r] + bh[r];
    }
}

// =====================================================================
// Phase 1: tensor-core GEMM  xpT[t][g][b] = x @ Wx^T + bias  (R9, passing)
// =====================================================================
__global__ __launch_bounds__(256, 2) void xp_mma() {
    __shared__ unsigned short As[2][2][128 * BKS];
    __shared__ unsigned short Bs[2][2][128 * BKS];

    const int tid = threadIdx.x;
    const int bn  = blockIdx.x;
    const int bm  = blockIdx.y;
    const int row0 = bm * 128;
    const int col0 = bn * 128;

    const int ln  = tid & 31, w = tid >> 5;
    const int wm  = w & 1;
    const int wn  = w >> 1;
    const int gid = ln >> 2, tig = ln & 3;

    auto stage = [&](int buf, int ks) {
        #pragma unroll
        for (int i = 0; i < 2; i++) {
            int idx = tid + i * 256;
            int pl = idx >> 8, row = (idx & 255) >> 1, ch = idx & 1;
            unsigned dst = smem_u32(&As[buf][pl][row * BKS]) + (unsigned)(ch * 16);
            const unsigned short* src = (pl ? g_xlo : g_xhi)
                + (size_t)(row0 + row) * IN_SZ + ks * 16 + ch * 8;
            cp_async16(dst, src);
        }
        #pragma unroll
        for (int i = 0; i < 2; i++) {
            int idx = tid + i * 256;
            int pl = idx >> 8, row = (idx & 255) >> 1, ch = idx & 1;
            unsigned dst = smem_u32(&Bs[buf][pl][row * BKS]) + (unsigned)(ch * 16);
            const unsigned short* src = (pl ? g_wlo : g_whi)
                + (size_t)(col0 + row) * IN_SZ + ks * 16 + ch * 8;
            cp_async16(dst, src);
        }
    };

    float acc[4][4][4];
    #pragma unroll
    for (int mf = 0; mf < 4; mf++)
        #pragma unroll
        for (int nf = 0; nf < 4; nf++)
            #pragma unroll
            for (int q = 0; q < 4; q++) acc[mf][nf][q] = 0.0f;

    stage(0, 0);
    cp_commit();

    const int NK = IN_SZ / 16;
    for (int ks = 0; ks < NK; ks++) {
        if (ks + 1 < NK) { stage((ks + 1) & 1, ks + 1); cp_commit(); cp_wait_n(1); }
        else             { cp_wait_n(0); }
        __syncthreads();

        const int buf = ks & 1;
        unsigned a_hi[4][4], a_lo[4][4];
        #pragma unroll
        for (int mf = 0; mf < 4; mf++) {
            int r0 = (wm * 64 + mf * 16 + gid) * BKS + 2 * tig;
            int r8 = r0 + 8 * BKS;
            a_hi[mf][0] = *(const unsigned*)&As[buf][0][r0];
            a_hi[mf][1] = *(const unsigned*)&As[buf][0][r8];
            a_hi[mf][2] = *(const unsigned*)&As[buf][0][r0 + 8];
            a_hi[mf][3] = *(const unsigned*)&As[buf][0][r8 + 8];
            a_lo[mf][0] = *(const unsigned*)&As[buf][1][r0];
            a_lo[mf][1] = *(const unsigned*)&As[buf][1][r8];
            a_lo[mf][2] = *(const unsigned*)&As[buf][1][r0 + 8];
            a_lo[mf][3] = *(const unsigned*)&As[buf][1][r8 + 8];
        }
        #pragma unroll
        for (int nf = 0; nf < 4; nf++) {
            int r = (wn * 32 + nf * 8 + gid) * BKS + 2 * tig;
            unsigned bh0 = *(const unsigned*)&Bs[buf][0][r];
            unsigned bh1 = *(const unsigned*)&Bs[buf][0][r + 8];
            unsigned bl0 = *(const unsigned*)&Bs[buf][1][r];
            unsigned bl1 = *(const unsigned*)&Bs[buf][1][r + 8];
            #pragma unroll
            for (int mf = 0; mf < 4; mf++) {
                mma16816(acc[mf][nf], a_hi[mf], bh0, bh1);
                mma16816(acc[mf][nf], a_lo[mf], bh0, bh1);
                mma16816(acc[mf][nf], a_hi[mf], bl0, bl1);
            }
        }
        __syncthreads();
    }

    #pragma unroll
    for (int nf = 0; nf < 4; nf++) {
        int n0 = col0 + wn * 32 + nf * 8 + 2 * tig;
        float bz0 = g_bias[n0], bz1 = g_bias[n0 + 1];
        #pragma unroll
        for (int mf = 0; mf < 4; mf++) {
            int m0 = row0 + wm * 64 + mf * 16 + gid;
            size_t t0 = (size_t)(m0 >> 6);
            int b0 = m0 & 63;
            size_t base = (t0 * G4 + n0) * B_SZ + b0;
            g_xpT[base]          = acc[mf][nf][0] + bz0;
            g_xpT[base + B_SZ]   = acc[mf][nf][1] + bz1;
            g_xpT[base + 8]      = acc[mf][nf][2] + bz0;
            g_xpT[base + B_SZ+8] = acc[mf][nf][3] + bz1;
        }
    }
}

// =====================================================================
// Phase 2: persistent recurrence. R9 staggered schedule with the halves'
// LATENCY pipelined: both polls in parallel, both h-stages issued as two
// cp.async groups; A's MMA/gate/release (mid-step) overlap B's staging.
// =====================================================================
__global__ __launch_bounds__(512, 1) void lstm_rec(
    const float* __restrict__ Whf, const float* __restrict__ Whi,
    const float* __restrict__ Who, const float* __restrict__ Whg,
    float* __restrict__ out)
{
    __shared__ unsigned short hsA[2][BPS * HSP];
    __shared__ unsigned short hsB[2][BPS * HSP];
    __shared__ float zpA[4][64][8];
    __shared__ float zpB[4][64][8];

    const int tid = threadIdx.x;
    const int ct  = blockIdx.x;
    const int cw  = ct & 31;
    const int sA  = (ct >> 5) * 2;
    const int sB  = sA + 1;
    const int j0  = cw * UPC;
    const int B0A = sA * BPS;
    const int B0B = sB * BPS;

    const int w   = tid >> 5;
    const int mt  = w & 3;
    const int kw  = w >> 2;
    const int ln  = tid & 31;
    const int g   = ln >> 2;
    const int t2  = ln & 3;

    const float* whp = (mt == 0) ? Whf : (mt == 1) ? Whi : (mt == 2) ? Who : Whg;
    unsigned a_hi[8][4], a_lo[8][4];
    {
        const float* Wr  = whp + (size_t)(j0 + g) * H_SZ;
        const float* Wr8 = whp + (size_t)(j0 + g + 8) * H_SZ;
        #pragma unroll
        for (int kt = 0; kt < 8; kt++) {
            int kb = kw * 128 + kt * 16 + 2 * t2;
            split2(*(const float2*)&Wr [kb],     a_hi[kt][0], a_lo[kt][0]);
            split2(*(const float2*)&Wr8[kb],     a_hi[kt][1], a_lo[kt][1]);
            split2(*(const float2*)&Wr [kb + 8], a_hi[kt][2], a_lo[kt][2]);
            split2(*(const float2*)&Wr8[kb + 8], a_hi[kt][3], a_lo[kt][3]);
        }
    }

    const unsigned baseA = flag_acquire(&g_arrive[sA * CPS + cw]);
    const unsigned baseB = flag_acquire(&g_arrive[sB * CPS + cw]);
    __syncthreads();

    const int ul = (tid & 127) >> 3;
    const int ub = tid & 7;
    float cA = 0.0f, cB = 0.0f;

    // staging helper: 1024 x 16B chunks into hs (2 per thread)
    auto stage_h = [&](unsigned short (*hs)[BPS * HSP], int s, int t) {
        const size_t srcb = (((size_t)(t - 1) * NSTR + s) * BPS) * H_SZ;
        #pragma unroll
        for (int i = 0; i < 2; i++) {
            int idx = tid + i * 512;
            int pl = idx >> 9;
            int b  = (idx >> 6) & 7;
            int c8 = idx & 63;
            unsigned dst = smem_u32(&hs[pl][0]) + (unsigned)(b * HSP + c8 * 8) * 2;
            const unsigned short* src = (pl ? g_hlo : g_hhi)
                                        + srcb + (size_t)b * H_SZ + c8 * 8;
            cp_async16(dst, src);
        }
    };
    // MMA helper for one stream
    auto h_mma = [&](unsigned short (*hs)[BPS * HSP], float (*zp)[64][8]) {
        float d[4] = {0.f, 0.f, 0.f, 0.f};
        const unsigned short* hr_hi = &hs[0][g * HSP];
        const unsigned short* hr_lo = &hs[1][g * HSP];
        #pragma unroll
        for (int kt = 0; kt < 8; kt++) {
            int kb = kw * 128 + kt * 16 + 2 * t2;
            unsigned bh0 = *(const unsigned*)&hr_hi[kb];
            unsigned bh1 = *(const unsigned*)&hr_hi[kb + 8];
            unsigned bl0 = *(const unsigned*)&hr_lo[kb];
            unsigned bl1 = *(const unsigned*)&hr_lo[kb + 8];
            mma16816(d, a_hi[kt], bh0, bh1);
            mma16816(d, a_lo[kt], bh0, bh1);
            mma16816(d, a_hi[kt], bl0, bl1);
        }
        *(float2*)&zp[kw][16 * mt + g][2 * t2]     = make_float2(d[0], d[1]);
        *(float2*)&zp[kw][16 * mt + g + 8][2 * t2] = make_float2(d[2], d[3]);
    };
    // gate helper (tid<128)
    auto gate = [&](float (*zp)[64][8], const float* xq, float& c, int s, int t) {
        float z[4];
        #pragma unroll
        for (int q = 0; q < 4; q++) {
            float v = xq[q];
            if (t > 0) {
                #pragma unroll
                for (int k4 = 0; k4 < 4; k4++)
                    v += zp[k4][16 * q + ul][ub];
            }
            z[q] = v;
        }
        float f  = sig_apx(z[0]);
        float ii = sig_apx(z[1]);
        float o  = sig_apx(z[2]);
        float gg = tanh_apx(z[3]);
        c        = fmaf(f, c, ii * gg);
        float h  = o * tanh_apx(c);
        int j = j0 + ul;
        int B = s * BPS + ub;
        out[((size_t)t * B_SZ + B) * H_SZ + j] = h;
        unsigned short hh, hl;
        split1(h, hh, hl);
        size_t hb = (((size_t)t * NSTR + s) * BPS + ub) * H_SZ + j;
        g_hhi[hb] = hh;
        g_hlo[hb] = hl;
        if (t == T_STEPS - 1) {
            size_t tail = (size_t)T_STEPS * B_SZ * H_SZ;
            out[tail + (size_t)B * H_SZ + j] = h;
            out[tail + (size_t)B_SZ * H_SZ + (size_t)B * H_SZ + j] = c;
        }
    };

    for (int t = 0; t < T_STEPS; t++) {
        // xp prefetch for both streams (independent of h)
        float xqA[4], xqB[4];
        if (tid < 128) {
            size_t xb = ((size_t)t * G4 + j0 + ul) * B_SZ;
            #pragma unroll
            for (int q = 0; q < 4; q++) {
                xqA[q] = g_xpT[xb + (size_t)q * 512 * B_SZ + B0A + ub];
                xqB[q] = g_xpT[xb + (size_t)q * 512 * B_SZ + B0B + ub];
            }
        }

        if (t > 0) {
            // parallel polls: lanes 0-31 -> A, 32-63 -> B
            if (tid < 2 * CPS) {
                const int ss = (tid < CPS) ? sA : sB;
                const unsigned tb = (tid < CPS) ? baseA : baseB;
                const unsigned* fp = &g_arrive[ss * CPS + (tid & 31)];
                unsigned target = tb + (unsigned)t;
                while ((int)(flag_acquire(fp) - target) < 0) { }
            }
            __syncthreads();

            // stage A then B as two cp.async groups
            stage_h(hsA, sA, t); cp_commit();
            stage_h(hsB, sB, t); cp_commit();

            cp_wait_n(1);            // A's data ready; B still in flight
            __syncthreads();
            h_mma(hsA, zpA);
            __syncthreads();
        }

        // gate A + release A (mid-step stagger, as in R9)
        if (tid < 128) gate(zpA, xqA, cA, sA, t);
        __syncthreads();
        if (tid == 0) flag_release(&g_arrive[sA * CPS + cw], baseA + (unsigned)t + 1u);

        if (t > 0) {
            cp_wait_n(0);            // B's data (landed during A's compute)
            __syncthreads();
            h_mma(hsB, zpB);
            __syncthreads();
        }

        // gate B + release B (end-step)
        if (tid < 128) gate(zpB, xqB, cB, sB, t);
        __syncthreads();
        if (tid == 0) flag_release(&g_arrive[sB * CPS + cw], baseB + (unsigned)t + 1u);
    }
}

// =====================================================================
extern "C" void kernel_launch(void* const* d_in, const int* in_sizes, int n_in,
                              void* d_out, int out_size)
{
    const float* x   = (const float*)d_in[0];
    const float* Wxf = (const float*)d_in[1];  const float* bxf = (const float*)d_in[2];
    const float* Whf = (const float*)d_in[3];  const float* bhf = (const float*)d_in[4];
    const float* Wxi = (const float*)d_in[5];  const float* bxi = (const float*)d_in[6];
    const float* Whi = (const float*)d_in[7];  const float* bhi = (const float*)d_in[8];
    const float* Wxo = (const float*)d_in[9];  const float* bxo = (const float*)d_in[10];
    const float* Who = (const float*)d_in[11]; const float* bho = (const float*)d_in[12];
    const float* Wxg = (const float*)d_in[13]; const float* bxg = (const float*)d_in[14];
    const float* Whg = (const float*)d_in[15]; const float* bhg = (const float*)d_in[16];
    float* out = (float*)d_out;

    convert_x<<<(MROWS * IN_SZ) / (256 * 4), 256>>>(x);
    convert_w<<<G4, 128>>>(Wxf, Wxi, Wxo, Wxg,
                           bxf, bxi, bxo, bxg,
                           bhf, bhi, bho, bhg);

    dim3 ggrid(G4 / 128, MROWS / 128);
    xp_mma<<<ggrid, 256>>>();

    lstm_rec<<<NCTA, 512>>>(Whf, Whi, Who, Whg, out);
}

// round 14
// speedup vs baseline: 1.8598x; 1.1761x over previous
#include <cuda_runtime.h>
#include <cuda_bf16.h>
#include <cstdint>

#define T_STEPS 1024
#define B_SZ    64
#define H_SZ    512
#define IN_SZ   512
#define G4      2048
#define NCTA    128
#define NSTR    8          // independent batch streams
#define CPS     32         // CTAs per stream
#define BPS     8          // batches per stream
#define UPC     16         // hidden units per CTA (64 gate-rows)
#define HSP     520        // padded hs row length (bf16) in lstm_rec

#define MROWS   65536      // T*B
#define BKS     24         // xp_mma smem row stride in ushorts (48 B, conflict-free)

// ---------------- scratch ----------------
__device__ float          g_xpT[(size_t)T_STEPS * G4 * B_SZ];             // [t][g][b]
__device__ unsigned short g_hhi[(size_t)T_STEPS * NSTR * BPS * H_SZ];     // h bf16 hi
__device__ unsigned short g_hlo[(size_t)T_STEPS * NSTR * BPS * H_SZ];     // h bf16 lo
__device__ unsigned       g_arrive[NSTR * CPS];                           // stream flags
__device__ unsigned short g_xhi[(size_t)MROWS * IN_SZ];                   // x bf16 hi
__device__ unsigned short g_xlo[(size_t)MROWS * IN_SZ];                   // x bf16 lo
__device__ unsigned short g_whi[(size_t)G4 * IN_SZ];                      // Wx bf16 hi
__device__ unsigned short g_wlo[(size_t)G4 * IN_SZ];                      // Wx bf16 lo
__device__ float          g_bias[G4];                                     // bx + bh

// ---------------- helpers ----------------
__device__ __forceinline__ float tanh_apx(float x) {
    float y; asm("tanh.approx.f32 %0, %1;" : "=f"(y) : "f"(x)); return y;
}
__device__ __forceinline__ float sig_apx(float x) {
    return fmaf(0.5f, tanh_apx(0.5f * x), 0.5f);
}
__device__ __forceinline__ unsigned smem_u32(const void* p) {
    return (unsigned)__cvta_generic_to_shared(p);
}
__device__ __forceinline__ void cp_async16(unsigned dst, const void* src) {
    asm volatile("cp.async.ca.shared.global [%0], [%1], 16;" :: "r"(dst), "l"(src));
}
__device__ __forceinline__ void cp_commit() {
    asm volatile("cp.async.commit_group;" ::: "memory");
}
__device__ __forceinline__ void cp_wait_n(int n) {
    if (n == 0) asm volatile("cp.async.wait_group 0;" ::: "memory");
    else        asm volatile("cp.async.wait_group 1;" ::: "memory");
}
__device__ __forceinline__ void cp_commit_wait() {
    asm volatile("cp.async.commit_group;\ncp.async.wait_group 0;" ::: "memory");
}
__device__ __forceinline__ void flag_release(unsigned* p, unsigned v) {
    asm volatile("st.release.gpu.global.u32 [%0], %1;" :: "l"(p), "r"(v) : "memory");
}
__device__ __forceinline__ unsigned flag_acquire(const unsigned* p) {
    unsigned v;
    asm volatile("ld.acquire.gpu.global.u32 %0, [%1];" : "=r"(v) : "l"(p) : "memory");
    return v;
}
__device__ __forceinline__ void split1(float v, unsigned short& hi, unsigned short& lo) {
    hi = __bfloat16_as_ushort(__float2bfloat16(v));
    float r = v - __bfloat162float(__ushort_as_bfloat16(hi));
    lo = __bfloat16_as_ushort(__float2bfloat16(r));
}
__device__ __forceinline__ void split2(float2 v, unsigned& hi, unsigned& lo) {
    unsigned short hx, lx, hy, ly;
    split1(v.x, hx, lx); split1(v.y, hy, ly);
    hi = (unsigned)hx | ((unsigned)hy << 16);
    lo = (unsigned)lx | ((unsigned)ly << 16);
}
__device__ __forceinline__ void mma16816(float* d, const unsigned* a,
                                         unsigned b0, unsigned b1) {
    asm volatile(
        "mma.sync.aligned.m16n8k16.row.col.f32.bf16.bf16.f32 "
        "{%0,%1,%2,%3}, {%4,%5,%6,%7}, {%8,%9}, {%0,%1,%2,%3};"
        : "+f"(d[0]), "+f"(d[1]), "+f"(d[2]), "+f"(d[3])
        : "r"(a[0]), "r"(a[1]), "r"(a[2]), "r"(a[3]), "r"(b0), "r"(b1));
}
__device__ __forceinline__ void ldsm_x4(unsigned& r0, unsigned& r1,
                                        unsigned& r2, unsigned& r3, unsigned addr) {
    asm volatile("ldmatrix.sync.aligned.m8n8.x4.shared.b16 {%0,%1,%2,%3}, [%4];"
                 : "=r"(r0), "=r"(r1), "=r"(r2), "=r"(r3) : "r"(addr));
}
__device__ __forceinline__ void ldsm_x2(unsigned& r0, unsigned& r1, unsigned addr) {
    asm volatile("ldmatrix.sync.aligned.m8n8.x2.shared.b16 {%0,%1}, [%2];"
                 : "=r"(r0), "=r"(r1) : "r"(addr));
}

// =====================================================================
// Converters: split fp32 -> bf16 hi/lo planes
// =====================================================================
__global__ __launch_bounds__(256) void convert_x(const float* __restrict__ x) {
    size_t i = ((size_t)blockIdx.x * 256 + threadIdx.x) * 4;
    float4 v = *(const float4*)&x[i];
    unsigned short h[4], l[4];
    split1(v.x, h[0], l[0]); split1(v.y, h[1], l[1]);
    split1(v.z, h[2], l[2]); split1(v.w, h[3], l[3]);
    *(ushort4*)&g_xhi[i] = make_ushort4(h[0], h[1], h[2], h[3]);
    *(ushort4*)&g_xlo[i] = make_ushort4(l[0], l[1], l[2], l[3]);
}

__global__ __launch_bounds__(128) void convert_w(
    const float* __restrict__ Wx0, const float* __restrict__ Wx1,
    const float* __restrict__ Wx2, const float* __restrict__ Wx3,
    const float* __restrict__ bx0, const float* __restrict__ bx1,
    const float* __restrict__ bx2, const float* __restrict__ bx3,
    const float* __restrict__ bh0, const float* __restrict__ bh1,
    const float* __restrict__ bh2, const float* __restrict__ bh3)
{
    int gidx = blockIdx.x;
    int gate = gidx >> 9, r = gidx & 511;
    const float* W = (gate == 0) ? Wx0 : (gate == 1) ? Wx1 : (gate == 2) ? Wx2 : Wx3;
    size_t base = (size_t)gidx * IN_SZ;
    for (int k = threadIdx.x * 4; k < IN_SZ; k += 128 * 4) {
        float4 v = *(const float4*)&W[(size_t)r * IN_SZ + k];
        unsigned short h[4], l[4];
        split1(v.x, h[0], l[0]); split1(v.y, h[1], l[1]);
        split1(v.z, h[2], l[2]); split1(v.w, h[3], l[3]);
        *(ushort4*)&g_whi[base + k] = make_ushort4(h[0], h[1], h[2], h[3]);
        *(ushort4*)&g_wlo[base + k] = make_ushort4(l[0], l[1], l[2], l[3]);
    }
    if (threadIdx.x == 0) {
        const float* bx = (gate == 0) ? bx0 : (gate == 1) ? bx1 : (gate == 2) ? bx2 : bx3;
        const float* bh = (gate == 0) ? bh0 : (gate == 1) ? bh1 : (gate == 2) ? bh2 : bh3;
        g_bias[gidx] = bx[r] + bh[r];
    }
}

// =====================================================================
// Phase 1: tensor-core GEMM  xpT[t][g][b] = x @ Wx^T + bias
// R9 structure; fragment loads via ldmatrix (16 LDSM vs 48 LDS per iter).
// =====================================================================
__global__ __launch_bounds__(256, 2) void xp_mma() {
    __shared__ unsigned short As[2][2][128 * BKS];
    __shared__ unsigned short Bs[2][2][128 * BKS];

    const int tid = threadIdx.x;
    const int bn  = blockIdx.x;
    const int bm  = blockIdx.y;
    const int row0 = bm * 128;
    const int col0 = bn * 128;

    const int ln  = tid & 31, w = tid >> 5;
    const int wm  = w & 1;
    const int wn  = w >> 1;
    const int gid = ln >> 2, tig = ln & 3;

    // ldmatrix per-lane offsets (ushort units -> bytes at use)
    // A (x4): matrices {r0-7 k0-7, r8-15 k0-7, r0-7 k8-15, r8-15 k8-15}
    const int a_row = wm * 64 + (ln & 7) + ((ln >> 3) & 1) * 8;
    const int a_kof = (ln >> 4) * 8;
    const unsigned a_off = (unsigned)((a_row * BKS + a_kof) * 2);
    // B (x2): matrices {n0-7 k0-7, n0-7 k8-15}; lanes 16+ unused (kept in-range)
    const int b_row = wn * 32 + (ln & 7);
    const int b_kof = ((ln >> 3) & 1) * 8;
    const unsigned b_off = (unsigned)((b_row * BKS + b_kof) * 2);

    auto stage = [&](int buf, int ks) {
        #pragma unroll
        for (int i = 0; i < 2; i++) {
            int idx = tid + i * 256;
            int pl = idx >> 8, row = (idx & 255) >> 1, ch = idx & 1;
            unsigned dst = smem_u32(&As[buf][pl][row * BKS]) + (unsigned)(ch * 16);
            const unsigned short* src = (pl ? g_xlo : g_xhi)
                + (size_t)(row0 + row) * IN_SZ + ks * 16 + ch * 8;
            cp_async16(dst, src);
        }
        #pragma unroll
        for (int i = 0; i < 2; i++) {
            int idx = tid + i * 256;
            int pl = idx >> 8, row = (idx & 255) >> 1, ch = idx & 1;
            unsigned dst = smem_u32(&Bs[buf][pl][row * BKS]) + (unsigned)(ch * 16);
            const unsigned short* src = (pl ? g_wlo : g_whi)
                + (size_t)(col0 + row) * IN_SZ + ks * 16 + ch * 8;
            cp_async16(dst, src);
        }
    };

    float acc[4][4][4];
    #pragma unroll
    for (int mf = 0; mf < 4; mf++)
        #pragma unroll
        for (int nf = 0; nf < 4; nf++)
            #pragma unroll
            for (int q = 0; q < 4; q++) acc[mf][nf][q] = 0.0f;

    stage(0, 0);
    cp_commit();

    const int NK = IN_SZ / 16;
    for (int ks = 0; ks < NK; ks++) {
        if (ks + 1 < NK) { stage((ks + 1) & 1, ks + 1); cp_commit(); cp_wait_n(1); }
        else             { cp_wait_n(0); }
        __syncthreads();

        const int buf = ks & 1;
        const unsigned a_hi_base = smem_u32(&As[buf][0][0]) + a_off;
        const unsigned a_lo_base = smem_u32(&As[buf][1][0]) + a_off;
        const unsigned b_hi_base = smem_u32(&Bs[buf][0][0]) + b_off;
        const unsigned b_lo_base = smem_u32(&Bs[buf][1][0]) + b_off;
        const unsigned A_MF = (unsigned)(16 * BKS * 2);  // 16 rows per mf
        const unsigned B_NF = (unsigned)(8 * BKS * 2);   // 8 rows per nf

        unsigned a_hi[4][4], a_lo[4][4];
        #pragma unroll
        for (int mf = 0; mf < 4; mf++) {
            ldsm_x4(a_hi[mf][0], a_hi[mf][1], a_hi[mf][2], a_hi[mf][3],
                    a_hi_base + (unsigned)mf * A_MF);
            ldsm_x4(a_lo[mf][0], a_lo[mf][1], a_lo[mf][2], a_lo[mf][3],
                    a_lo_base + (unsigned)mf * A_MF);
        }
        #pragma unroll
        for (int nf = 0; nf < 4; nf++) {
            unsigned bh0, bh1, bl0, bl1;
            ldsm_x2(bh0, bh1, b_hi_base + (unsigned)nf * B_NF);
            ldsm_x2(bl0, bl1, b_lo_base + (unsigned)nf * B_NF);
            #pragma unroll
            for (int mf = 0; mf < 4; mf++) {
                mma16816(acc[mf][nf], a_hi[mf], bh0, bh1);
                mma16816(acc[mf][nf], a_lo[mf], bh0, bh1);
                mma16816(acc[mf][nf], a_hi[mf], bl0, bl1);
            }
        }
        __syncthreads();
    }

    #pragma unroll
    for (int nf = 0; nf < 4; nf++) {
        int n0 = col0 + wn * 32 + nf * 8 + 2 * tig;
        float bz0 = g_bias[n0], bz1 = g_bias[n0 + 1];
        #pragma unroll
        for (int mf = 0; mf < 4; mf++) {
            int m0 = row0 + wm * 64 + mf * 16 + gid;
            size_t t0 = (size_t)(m0 >> 6);
            int b0 = m0 & 63;
            size_t base = (t0 * G4 + n0) * B_SZ + b0;
            g_xpT[base]          = acc[mf][nf][0] + bz0;
            g_xpT[base + B_SZ]   = acc[mf][nf][1] + bz1;
            g_xpT[base + 8]      = acc[mf][nf][2] + bz0;
            g_xpT[base + B_SZ+8] = acc[mf][nf][3] + bz1;
        }
    }
}

// =====================================================================
// Phase 2: persistent recurrence — EXACT R9 version (3.99 ms, passing).
// =====================================================================
__global__ __launch_bounds__(512, 1) void lstm_rec(
    const float* __restrict__ Whf, const float* __restrict__ Whi,
    const float* __restrict__ Who, const float* __restrict__ Whg,
    float* __restrict__ out)
{
    __shared__ unsigned short hsA[2][BPS * HSP];
    __shared__ unsigned short hsB[2][BPS * HSP];
    __shared__ float zpart[4][64][8];

    const int tid = threadIdx.x;
    const int ct  = blockIdx.x;
    const int cw  = ct & 31;
    const int sA  = (ct >> 5) * 2;
    const int sB  = sA + 1;
    const int j0  = cw * UPC;
    const int B0A = sA * BPS;
    const int B0B = sB * BPS;

    const int w   = tid >> 5;
    const int mt  = w & 3;
    const int kw  = w >> 2;
    const int ln  = tid & 31;
    const int g   = ln >> 2;
    const int t2  = ln & 3;

    const float* whp = (mt == 0) ? Whf : (mt == 1) ? Whi : (mt == 2) ? Who : Whg;
    unsigned a_hi[8][4], a_lo[8][4];
    {
        const float* Wr  = whp + (size_t)(j0 + g) * H_SZ;
        const float* Wr8 = whp + (size_t)(j0 + g + 8) * H_SZ;
        #pragma unroll
        for (int kt = 0; kt < 8; kt++) {
            int kb = kw * 128 + kt * 16 + 2 * t2;
            split2(*(const float2*)&Wr [kb],     a_hi[kt][0], a_lo[kt][0]);
            split2(*(const float2*)&Wr8[kb],     a_hi[kt][1], a_lo[kt][1]);
            split2(*(const float2*)&Wr [kb + 8], a_hi[kt][2], a_lo[kt][2]);
            split2(*(const float2*)&Wr8[kb + 8], a_hi[kt][3], a_lo[kt][3]);
        }
    }

    const unsigned baseA = flag_acquire(&g_arrive[sA * CPS + cw]);
    const unsigned baseB = flag_acquire(&g_arrive[sB * CPS + cw]);
    __syncthreads();

    const int ul = tid >> 3;
    const int ub = tid & 7;
    float cA = 0.0f, cB = 0.0f;

    for (int t = 0; t < T_STEPS; t++) {
        float xqA[4], xqB[4];
        if (tid < 128) {
            size_t xb = ((size_t)t * G4 + j0 + ul) * B_SZ;
            #pragma unroll
            for (int q = 0; q < 4; q++) {
                xqA[q] = g_xpT[xb + (size_t)q * 512 * B_SZ + B0A + ub];
                xqB[q] = g_xpT[xb + (size_t)q * 512 * B_SZ + B0B + ub];
            }
        }

        #pragma unroll
        for (int half = 0; half < 2; half++) {
            const int       s    = half ? sB : sA;
            unsigned short (*hs)[BPS * HSP] = half ? hsB : hsA;
            const unsigned  base = half ? baseB : baseA;
            const int       B0   = half ? B0B : B0A;
            float&          c    = half ? cB : cA;
            const float*    xq   = half ? xqB : xqA;

            if (t > 0) {
                if (tid < CPS) {
                    const unsigned* fp = &g_arrive[s * CPS + tid];
                    unsigned target = base + (unsigned)t;
                    while ((int)(flag_acquire(fp) - target) < 0) { }
                }
                __syncthreads();

                {
                    const size_t srcb = (((size_t)(t - 1) * NSTR + s) * BPS) * H_SZ;
                    const unsigned d_hi = smem_u32(&hs[0][0]);
                    const unsigned d_lo = smem_u32(&hs[1][0]);
                    #pragma unroll
                    for (int i = 0; i < 2; i++) {
                        int idx = tid + i * 512;
                        int pl = idx >> 9;
                        int b  = (idx >> 6) & 7;
                        int c8 = idx & 63;
                        unsigned dst = (pl ? d_lo : d_hi) + (unsigned)(b * HSP + c8 * 8) * 2;
                        const unsigned short* src = (pl ? g_hlo : g_hhi)
                                                    + srcb + (size_t)b * H_SZ + c8 * 8;
                        cp_async16(dst, src);
                    }
                }
                cp_commit_wait();
                __syncthreads();

                float d[4] = {0.f, 0.f, 0.f, 0.f};
                const unsigned short* hrow_hi = &hs[0][g * HSP];
                const unsigned short* hrow_lo = &hs[1][g * HSP];
                #pragma unroll
                for (int kt = 0; kt < 8; kt++) {
                    int kb = kw * 128 + kt * 16 + 2 * t2;
                    unsigned bh0 = *(const unsigned*)&hrow_hi[kb];
                    unsigned bh1 = *(const unsigned*)&hrow_hi[kb + 8];
                    unsigned bl0 = *(const unsigned*)&hrow_lo[kb];
                    unsigned bl1 = *(const unsigned*)&hrow_lo[kb + 8];
                    mma16816(d, a_hi[kt], bh0, bh1);
                    mma16816(d, a_lo[kt], bh0, bh1);
                    mma16816(d, a_hi[kt], bl0, bl1);
                }

                *(float2*)&zpart[kw][16 * mt + g][2 * t2]     = make_float2(d[0], d[1]);
                *(float2*)&zpart[kw][16 * mt + g + 8][2 * t2] = make_float2(d[2], d[3]);
            }
            __syncthreads();

            if (tid < 128) {
                float z[4];
                #pragma unroll
                for (int q = 0; q < 4; q++) {
                    float v = xq[q];
                    if (t > 0) {
                        #pragma unroll
                        for (int k4 = 0; k4 < 4; k4++)
                            v += zpart[k4][16 * q + ul][ub];
                    }
                    z[q] = v;
                }
                float f  = sig_apx(z[0]);
                float ii = sig_apx(z[1]);
                float o  = sig_apx(z[2]);
                float gg = tanh_apx(z[3]);
                c        = fmaf(f, c, ii * gg);
                float h  = o * tanh_apx(c);
                int j = j0 + ul;
                int B = B0 + ub;
                out[((size_t)t * B_SZ + B) * H_SZ + j] = h;
                unsigned short hh, hl;
                split1(h, hh, hl);
                size_t hb = (((size_t)t * NSTR + s) * BPS + ub) * H_SZ + j;
                g_hhi[hb] = hh;
                g_hlo[hb] = hl;
                if (t == T_STEPS - 1) {
                    size_t tail = (size_t)T_STEPS * B_SZ * H_SZ;
                    out[tail + (size_t)B * H_SZ + j] = h;
                    out[tail + (size_t)B_SZ * H_SZ + (size_t)B * H_SZ + j] = c;
                }
            }
            __syncthreads();
            if (tid == 0)
                flag_release(&g_arrive[s * CPS + cw], base + (unsigned)t + 1u);
        }
    }
}

// =====================================================================
extern "C" void kernel_launch(void* const* d_in, const int* in_sizes, int n_in,
                              void* d_out, int out_size)
{
    const float* x   = (const float*)d_in[0];
    const float* Wxf = (const float*)d_in[1];  const float* bxf = (const float*)d_in[2];
    const float* Whf = (const float*)d_in[3];  const float* bhf = (const float*)d_in[4];
    const float* Wxi = (const float*)d_in[5];  const float* bxi = (const float*)d_in[6];
    const float* Whi = (const float*)d_in[7];  const float* bhi = (const float*)d_in[8];
    const float* Wxo = (const float*)d_in[9];  const float* bxo = (const float*)d_in[10];
    const float* Who = (const float*)d_in[11]; const float* bho = (const float*)d_in[12];
    const float* Wxg = (const float*)d_in[13]; const float* bxg = (const float*)d_in[14];
    const float* Whg = (const float*)d_in[15]; const float* bhg = (const float*)d_in[16];
    float* out = (float*)d_out;

    convert_x<<<(MROWS * IN_SZ) / (256 * 4), 256>>>(x);
    convert_w<<<G4, 128>>>(Wxf, Wxi, Wxo, Wxg,
                           bxf, bxi, bxo, bxg,
                           bhf, bhi, bho, bhg);

    dim3 ggrid(G4 / 128, MROWS / 128);
    xp_mma<<<ggrid, 256>>>();

    lstm_rec<<<NCTA, 512>>>(Whf, Whi, Who, Whg, out);
}